// round 14
// baseline (speedup 1.0000x reference)
#include <cuda_runtime.h>
#include <cstdint>

#define E_NUM 1024
#define D_DIM 256
#define N_TOT 32768
#define ZQ_ELEMS 8388608
#define DECAY_F 0.99f
#define OMD_F 0.01f
#define FLT_BIG 3.4e38f
#define QS 26.0f
#define C2S2 (2.0f / 676.0f)

// ---- dynamic smem layout (main kernel) ----
#define SMEM_A_OFF    0        // 32768 : A 128 rows x 256 s8, swizzled
#define SMEM_B_OFF    32768    // 65536 : B double buffer, 2 x (128 codes x 256 s8)
#define SMEM_CAND_OFF 98304    // 5120  : cand [128 rows][2 halves][5] u32
#define SMEM_TOTAL    103424

// -------- device scratch (no allocations allowed) --------
__device__ float g_counts[E_NUM];
__device__ __align__(16) float g_embed[E_NUM * D_DIM];
__device__ float g_csq[E_NUM];
__device__ float g_loss;
__device__ float g_nb;
__device__ __align__(16) unsigned char g_cbi8[E_NUM * D_DIM];   // codebook s8

// -------- helpers --------
__device__ __forceinline__ uint32_t smem_u32(const void* p) {
    uint32_t a;
    asm("{ .reg .u64 t; cvta.to.shared.u64 t, %1; cvt.u32.u64 %0, t; }" : "=r"(a) : "l"(p));
    return a;
}
__device__ __forceinline__ unsigned q4(float4 v) {
    int a = __float2int_rn(fminf(fmaxf(v.x * QS, -127.f), 127.f));
    int b = __float2int_rn(fminf(fmaxf(v.y * QS, -127.f), 127.f));
    int c = __float2int_rn(fminf(fmaxf(v.z * QS, -127.f), 127.f));
    int d = __float2int_rn(fminf(fmaxf(v.w * QS, -127.f), 127.f));
    return (unsigned)(a & 255) | ((unsigned)(b & 255) << 8) |
           ((unsigned)(c & 255) << 16) | ((unsigned)d << 24);
}
__device__ __forceinline__ void mma_s8(int* c, unsigned a0, unsigned a1, unsigned a2,
                                       unsigned a3, unsigned b0, unsigned b1) {
    asm volatile("mma.sync.aligned.m16n8k32.row.col.s32.s8.s8.s32 "
        "{%0,%1,%2,%3}, {%4,%5,%6,%7}, {%8,%9}, {%0,%1,%2,%3};"
        : "+r"(c[0]), "+r"(c[1]), "+r"(c[2]), "+r"(c[3])
        : "r"(a0), "r"(a1), "r"(a2), "r"(a3), "r"(b0), "r"(b1));
}
#define LDSM4(r0,r1,r2,r3,addr) \
    asm volatile("ldmatrix.sync.aligned.m8n8.x4.shared.b16 {%0,%1,%2,%3}, [%4];" \
        : "=r"(r0), "=r"(r1), "=r"(r2), "=r"(r3) : "r"(addr))
__device__ __forceinline__ void cp16(unsigned dst, const void* src) {
    asm volatile("cp.async.ca.shared.global [%0], [%1], 16;"
                 :: "r"(dst), "l"(__cvta_generic_to_global(src)) : "memory");
}
#define CP_COMMIT() asm volatile("cp.async.commit_group;" ::: "memory")
#define CP_WAIT0()  asm volatile("cp.async.wait_group 0;" ::: "memory")

// u32 key: orderable-f32(dist) top 22 bits | idx (10 bits). ascending == (dist, idx)
__device__ __forceinline__ unsigned packdi(float d, int idx) {
    unsigned u = __float_as_uint(d);
    u ^= (unsigned)(((int)u) >> 31) | 0x80000000u;
    return (u & 0xFFFFFC00u) | (unsigned)idx;
}
__device__ __forceinline__ void ins5(unsigned v, unsigned* p) {
    if (v < p[4]) {
        p[4] = v;
        unsigned t;
        if (p[4] < p[3]) { t = p[3]; p[3] = p[4]; p[4] = t; }
        if (p[3] < p[2]) { t = p[2]; p[2] = p[3]; p[3] = t; }
        if (p[2] < p[1]) { t = p[1]; p[1] = p[2]; p[2] = t; }
        if (p[1] < p[0]) { t = p[0]; p[0] = p[1]; p[1] = t; }
    }
}

// -------- csq + s8 codebook + zero stats + ema_cs pre-sum --------
// grid 257 x 128: blocks 0-255 -> 4 codes (warp per code); block 256 -> ema sum
__global__ void csq_kernel(const float* __restrict__ cb, const float* __restrict__ ema_cs) {
    int b = blockIdx.x;
    int warp = threadIdx.x >> 5;
    int lane = threadIdx.x & 31;
    if (b < 256) {
        int e = b * 4 + warp;
        const float4* src = (const float4*)&cb[(size_t)e * D_DIM];
        float4 v0 = src[lane * 2], v1 = src[lane * 2 + 1];
        *(uint2*)&g_cbi8[(size_t)e * D_DIM + lane * 8] = make_uint2(q4(v0), q4(v1));
        float s = v0.x*v0.x + v0.y*v0.y + v0.z*v0.z + v0.w*v0.w
                + v1.x*v1.x + v1.y*v1.y + v1.z*v1.z + v1.w*v1.w;
        #pragma unroll
        for (int o = 16; o; o >>= 1) s += __shfl_xor_sync(0xffffffffu, s, o);
        float4 z4 = make_float4(0.f, 0.f, 0.f, 0.f);
        ((float4*)&g_embed[(size_t)e * D_DIM])[lane]      = z4;
        ((float4*)&g_embed[(size_t)e * D_DIM])[lane + 32] = z4;
        if (lane == 0) { g_csq[e] = s; g_counts[e] = 0.f; }
    } else {
        __shared__ float ws[4];
        float s = 0.f;
        for (int i = threadIdx.x; i < E_NUM; i += 128) s += ema_cs[i];
        #pragma unroll
        for (int o = 16; o; o >>= 1) s += __shfl_xor_sync(0xffffffffu, s, o);
        if (lane == 0) ws[warp] = s;
        __syncthreads();
        if (threadIdx.x == 0) {
            g_nb = ws[0] + ws[1] + ws[2] + ws[3];
            g_loss = 0.f;
        }
    }
}

// -------- s8 IMMA distance-GEMM + register top-5 + fused exact rescore --------
// 256 threads = 8 warps; block tile 128 rows x 128 codes; warp tile 32x64.
// B streamed as FULL e-tiles (8 stages, double buffered, 32 KB each).
__global__ __launch_bounds__(256, 2) void vq_main_kernel(
    const float* __restrict__ z, const float* __restrict__ cb,
    float* __restrict__ idx_f_out, float* __restrict__ zq_out)
{
    extern __shared__ char smem[];
    const uint32_t sb  = smem_u32(smem);
    const uint32_t sbA = sb + SMEM_A_OFF;
    const uint32_t sbB = sb + SMEM_B_OFF;
    unsigned* candsm = (unsigned*)(smem + SMEM_CAND_OFF);

    const int tid  = threadIdx.x;
    const int warp = tid >> 5;
    const int lane = tid & 31;
    const int tig  = lane & 3;
    const int grp  = lane >> 2;
    const int warp_m = (warp & 3) * 32;
    const int wn     = warp >> 2;        // 0/1: column half
    const int warp_n = wn * 64;
    const int row0 = blockIdx.x * 128;

    // fragment bases (xor swizzle key = lane&7 for both A and B rows)
    const int asw = lane & 7;
    const int akc = lane >> 4;           // A k-chunk within granule
    const int bkc = (lane >> 3) & 1;     // B k-chunk within granule
    uint32_t aB[2];
    #pragma unroll
    for (int mf = 0; mf < 2; mf++)
        aB[mf] = sbA + (warp_m + mf * 16 + ((lane >> 3) & 1) * 8 + (lane & 7)) * 256;
    uint32_t bBp[4];
    #pragma unroll
    for (int p = 0; p < 4; p++)
        bBp[p] = (uint32_t)((warp_n + p * 16 + ((lane >> 4) & 1) * 8 + (lane & 7)) * 256);

    // ---- A staging: z rows -> s8 swizzled smem (2048 granules of 16B) ----
    #pragma unroll 2
    for (int i = 0; i < 8; i++) {
        int li = tid + i * 256;
        int r = li >> 4, ch = li & 15;
        const float4* s = (const float4*)&z[(size_t)(row0 + r) * D_DIM + ch * 16];
        uint4 o = make_uint4(q4(s[0]), q4(s[1]), q4(s[2]), q4(s[3]));
        *(uint4*)(smem + SMEM_A_OFF + r * 256 + ((ch ^ (r & 7)) << 4)) = o;
    }
    // ---- B stage 0 via cp.async (full tile 0: 32 KB) ----
    {
        const char* src = (const char*)g_cbi8;
        #pragma unroll
        for (int i = 0; i < 8; i++) {
            int li = tid + i * 256;
            int r = li >> 4, ch = li & 15;
            cp16(sbB + r * 256 + ((ch ^ (r & 7)) << 4), src + (size_t)r * 256 + ch * 16);
        }
        CP_COMMIT();
    }
    CP_WAIT0();
    __syncthreads();

    int acc[2][8][4];
    #pragma unroll
    for (int mf = 0; mf < 2; mf++)
        #pragma unroll
        for (int nf = 0; nf < 8; nf++)
            #pragma unroll
            for (int q = 0; q < 4; q++) acc[mf][nf][q] = 0;

    // persistent per-thread top-5 (u32 packed) for 4 row-slots
    unsigned P[4][5];
    #pragma unroll
    for (int s = 0; s < 4; s++)
        #pragma unroll
        for (int q = 0; q < 5; q++) P[s][q] = ~0u;

    int pb = 0;
    #pragma unroll 1
    for (int st = 0; st < 8; st++) {
        // issue next B tile
        if (st < 7) {
            const char* src = (const char*)g_cbi8 + (size_t)(st + 1) * 128 * 256;
            uint32_t dstb = sbB + (pb ^ 1) * 32768;
            #pragma unroll
            for (int i = 0; i < 8; i++) {
                int li = tid + i * 256;
                int r = li >> 4, ch = li & 15;
                cp16(dstb + r * 256 + ((ch ^ (r & 7)) << 4), src + (size_t)r * 256 + ch * 16);
            }
            CP_COMMIT();
        }

        // compute current tile: 8 k32 granules
        const uint32_t bbuf = sbB + pb * 32768;
        #pragma unroll
        for (int g = 0; g < 8; g++) {
            unsigned bb[4][4];
            #pragma unroll
            for (int p = 0; p < 4; p++)
                LDSM4(bb[p][0], bb[p][1], bb[p][2], bb[p][3],
                      bbuf + bBp[p] + ((((g << 1) + bkc) ^ asw) << 4));
            #pragma unroll
            for (int mf = 0; mf < 2; mf++) {
                unsigned a0, a1, a2, a3;
                LDSM4(a0, a1, a2, a3, aB[mf] + ((((g << 1) + akc) ^ asw) << 4));
                #pragma unroll
                for (int p = 0; p < 4; p++) {
                    mma_s8(acc[mf][p * 2],     a0, a1, a2, a3, bb[p][0], bb[p][1]);
                    mma_s8(acc[mf][p * 2 + 1], a0, a1, a2, a3, bb[p][2], bb[p][3]);
                }
            }
        }

        // ---- tile epilogue: distances -> per-thread register top-5 ----
        {
            int cbase = st * 128 + warp_n + tig * 2;
            #pragma unroll
            for (int nf = 0; nf < 8; nf++) {
                int ca = cbase + nf * 8;
                float cqa = __ldg(&g_csq[ca]);
                float cqb = __ldg(&g_csq[ca + 1]);
                #pragma unroll
                for (int mf = 0; mf < 2; mf++) {
                    #pragma unroll
                    for (int rh = 0; rh < 2; rh++) {
                        int s = mf * 2 + rh;
                        float d0 = fmaf((float)acc[mf][nf][rh * 2],     -C2S2, cqa);
                        float d1 = fmaf((float)acc[mf][nf][rh * 2 + 1], -C2S2, cqb);
                        ins5(packdi(d0, ca),     P[s]);
                        ins5(packdi(d1, ca + 1), P[s]);
                    }
                }
            }
            #pragma unroll
            for (int mf = 0; mf < 2; mf++)
                #pragma unroll
                for (int nf = 0; nf < 8; nf++)
                    #pragma unroll
                    for (int q = 0; q < 4; q++) acc[mf][nf][q] = 0;
        }

        CP_WAIT0();
        __syncthreads();
        pb ^= 1;
    }

    // ---- merge top-5 across tig lanes -> true half top-5 per row ----
    #pragma unroll
    for (int s = 0; s < 4; s++) {
        #pragma unroll
        for (int off = 1; off <= 2; off <<= 1) {
            unsigned ov[5];
            #pragma unroll
            for (int j = 0; j < 5; j++)
                ov[j] = __shfl_xor_sync(0xffffffffu, P[s][j], off);
            #pragma unroll
            for (int j = 0; j < 5; j++) ins5(ov[j], P[s]);
        }
        if (tig == 0) {
            int rl = warp_m + (s >> 1) * 16 + (s & 1) * 8 + grp;
            unsigned* c = candsm + (rl * 2 + wn) * 5;
            #pragma unroll
            for (int j = 0; j < 5; j++) c[j] = P[s][j];
        }
    }
    __syncthreads();

    // ---- fused exact fp32 rescore of 10 candidates + scatter ----
    float lsum_t = 0.f;
    #pragma unroll 1
    for (int j = 0; j < 16; j++) {
        int lrow = warp * 16 + j;
        int row  = row0 + lrow;
        const float4* zp = (const float4*)&z[(size_t)row * D_DIM];
        float4 x0 = zp[lane], x1 = zp[lane + 32];

        float bd = FLT_BIG;
        int   bi = 0x7fffffff;
        #pragma unroll
        for (int c = 0; c < 10; c++) {
            int e = (int)(candsm[lrow * 10 + c] & 1023u);
            const float4* cp = (const float4*)&cb[(size_t)e * D_DIM];
            float4 c0 = cp[lane], c1 = cp[lane + 32];
            float dot = x0.x*c0.x + x0.y*c0.y + x0.z*c0.z + x0.w*c0.w
                      + x1.x*c1.x + x1.y*c1.y + x1.z*c1.z + x1.w*c1.w;
            #pragma unroll
            for (int o = 16; o; o >>= 1) dot += __shfl_xor_sync(0xffffffffu, dot, o);
            float d = g_csq[e] - 2.f * dot;
            if (d < bd || (d == bd && e < bi)) { bd = d; bi = e; }
        }
        if (lane == 0) idx_f_out[row] = (float)bi;

        const float4* cp = (const float4*)&cb[(size_t)bi * D_DIM];
        float4 c0 = cp[lane], c1 = cp[lane + 32];
        float4 o0, o1;
        o0.x = x0.x + (c0.x - x0.x); o0.y = x0.y + (c0.y - x0.y);
        o0.z = x0.z + (c0.z - x0.z); o0.w = x0.w + (c0.w - x0.w);
        o1.x = x1.x + (c1.x - x1.x); o1.y = x1.y + (c1.y - x1.y);
        o1.z = x1.z + (c1.z - x1.z); o1.w = x1.w + (c1.w - x1.w);
        float4* qp = (float4*)&zq_out[(size_t)row * D_DIM];
        qp[lane] = o0; qp[lane + 32] = o1;

        float dx;
        dx = x0.x - c0.x; lsum_t += dx * dx;  dx = x0.y - c0.y; lsum_t += dx * dx;
        dx = x0.z - c0.z; lsum_t += dx * dx;  dx = x0.w - c0.w; lsum_t += dx * dx;
        dx = x1.x - c1.x; lsum_t += dx * dx;  dx = x1.y - c1.y; lsum_t += dx * dx;
        dx = x1.z - c1.z; lsum_t += dx * dx;  dx = x1.w - c1.w; lsum_t += dx * dx;

        float* ge = &g_embed[(size_t)bi * D_DIM];
        asm volatile("red.global.add.v4.f32 [%0], {%1,%2,%3,%4};"
                     :: "l"(ge + lane * 4), "f"(x0.x), "f"(x0.y), "f"(x0.z), "f"(x0.w) : "memory");
        asm volatile("red.global.add.v4.f32 [%0], {%1,%2,%3,%4};"
                     :: "l"(ge + (lane + 32) * 4), "f"(x1.x), "f"(x1.y), "f"(x1.z), "f"(x1.w) : "memory");
        if (lane == 0) atomicAdd(&g_counts[bi], 1.0f);
    }
    #pragma unroll
    for (int o = 16; o; o >>= 1) lsum_t += __shfl_xor_sync(0xffffffffu, lsum_t, o);
    if (lane == 0) atomicAdd(&g_loss, lsum_t);
}

// -------- merged finalize (vector loads, scalar stores: outputs odd-offset) --------
__global__ void finalize_kernel(const float* __restrict__ ema_cs,
                                const float* __restrict__ ema_es,
                                float* __restrict__ out_cb,
                                float* __restrict__ out_cs,
                                float* __restrict__ out_es,
                                float* __restrict__ out_loss)
{
    int e = blockIdx.x * 4 + (threadIdx.x >> 6);
    int q = threadIdx.x & 63;
    float n = DECAY_F * g_nb + OMD_F * (float)N_TOT;
    float ncs = DECAY_F * ema_cs[e] + OMD_F * g_counts[e];
    float inv_sm = (n + 1024.0f * 1e-5f) / ((ncs + 1e-5f) * n);
    size_t base = (size_t)e * D_DIM + q * 4;
    float4 es = *(const float4*)&ema_es[base];
    float4 ge = *(const float4*)&g_embed[base];
    float nes0 = DECAY_F * es.x + OMD_F * ge.x;
    float nes1 = DECAY_F * es.y + OMD_F * ge.y;
    float nes2 = DECAY_F * es.z + OMD_F * ge.z;
    float nes3 = DECAY_F * es.w + OMD_F * ge.w;
    out_es[base + 0] = nes0;  out_cb[base + 0] = nes0 * inv_sm;
    out_es[base + 1] = nes1;  out_cb[base + 1] = nes1 * inv_sm;
    out_es[base + 2] = nes2;  out_cb[base + 2] = nes2 * inv_sm;
    out_es[base + 3] = nes3;  out_cb[base + 3] = nes3 * inv_sm;
    if (q == 0) {
        out_cs[e] = ncs;
        if (e == 0) *out_loss = 0.5f * g_loss / (float)(N_TOT * D_DIM);
    }
}

extern "C" void kernel_launch(void* const* d_in, const int* in_sizes, int n_in,
                              void* d_out, int out_size)
{
    const float* z_e    = (const float*)d_in[0];
    const float* cb     = (const float*)d_in[1];
    const float* ema_cs = (const float*)d_in[2];
    const float* ema_es = (const float*)d_in[3];
    float* out = (float*)d_out;

    float* out_zq   = out;
    float* out_loss = out + ZQ_ELEMS;
    float* out_idx  = out + ZQ_ELEMS + 1;
    float* out_cb   = out + ZQ_ELEMS + 1 + N_TOT;
    float* out_cs   = out_cb + E_NUM * D_DIM;
    float* out_es   = out_cs + E_NUM;

    cudaFuncSetAttribute(vq_main_kernel,
                         cudaFuncAttributeMaxDynamicSharedMemorySize, SMEM_TOTAL);

    csq_kernel<<<257, 128>>>(cb, ema_cs);
    vq_main_kernel<<<N_TOT / 128, 256, SMEM_TOTAL>>>(z_e, cb, out_idx, out_zq);
    finalize_kernel<<<E_NUM / 4, 256>>>(ema_cs, ema_es, out_cb, out_cs, out_es, out_loss);
}

// round 15
// speedup vs baseline: 1.9555x; 1.9555x over previous
#include <cuda_runtime.h>
#include <cstdint>

#define E_NUM 1024
#define D_DIM 256
#define N_TOT 32768
#define ZQ_ELEMS 8388608
#define DECAY_F 0.99f
#define OMD_F 0.01f
#define FLT_BIG 3.4e38f
#define RESCORE_MARGIN 0.5f

// ---- dynamic smem layout (main kernel) ----
#define SMEM_A_OFF    0        // 65536 : A 128x256 bf16, swizzled
#define SMEM_B_OFF    65536    // 32768 : B double buffer, 2 x (128 codes x 64 k bf16)
#define SMEM_CAND_OFF 98304    // 3072  : cand [128 rows][2 halves][3] u32
#define SMEM_TOTAL    101376

// -------- device scratch (no allocations allowed) --------
__device__ float g_counts[E_NUM];
__device__ __align__(16) float g_embed[E_NUM * D_DIM];
__device__ float g_csq[E_NUM];
__device__ float g_loss;
__device__ float g_nb;
__device__ __align__(16) unsigned g_cbb32[E_NUM * D_DIM / 2];   // codebook bf16

// -------- helpers --------
__device__ __forceinline__ uint32_t smem_u32(const void* p) {
    uint32_t a;
    asm("{ .reg .u64 t; cvta.to.shared.u64 t, %1; cvt.u32.u64 %0, t; }" : "=r"(a) : "l"(p));
    return a;
}
__device__ __forceinline__ unsigned bpack(float lo, float hi) {
    unsigned r;
    asm("cvt.rn.bf16x2.f32 %0, %1, %2;" : "=r"(r) : "f"(hi), "f"(lo));
    return r;
}
__device__ __forceinline__ void mma_bf16(float* c, unsigned a0, unsigned a1, unsigned a2,
                                         unsigned a3, unsigned b0, unsigned b1) {
    asm volatile("mma.sync.aligned.m16n8k16.row.col.f32.bf16.bf16.f32 "
        "{%0,%1,%2,%3}, {%4,%5,%6,%7}, {%8,%9}, {%0,%1,%2,%3};"
        : "+f"(c[0]), "+f"(c[1]), "+f"(c[2]), "+f"(c[3])
        : "r"(a0), "r"(a1), "r"(a2), "r"(a3), "r"(b0), "r"(b1));
}
#define LDSM4(r0,r1,r2,r3,addr) \
    asm volatile("ldmatrix.sync.aligned.m8n8.x4.shared.b16 {%0,%1,%2,%3}, [%4];" \
        : "=r"(r0), "=r"(r1), "=r"(r2), "=r"(r3) : "r"(addr))
__device__ __forceinline__ void cp16(unsigned dst, const void* src) {
    asm volatile("cp.async.ca.shared.global [%0], [%1], 16;"
                 :: "r"(dst), "l"(__cvta_generic_to_global(src)) : "memory");
}
#define CP_COMMIT() asm volatile("cp.async.commit_group;" ::: "memory")
#define CP_WAIT0()  asm volatile("cp.async.wait_group 0;" ::: "memory")

// u32 key: orderable-f32(dist) top 22 bits | idx (10 bits). ascending == (dist, idx)
__device__ __forceinline__ unsigned packdi(float d, int idx) {
    unsigned u = __float_as_uint(d);
    u ^= (unsigned)(((int)u) >> 31) | 0x80000000u;
    return (u & 0xFFFFFC00u) | (unsigned)idx;
}
__device__ __forceinline__ float unpackd(unsigned k) {
    unsigned u = k & 0xFFFFFC00u;
    u = (u & 0x80000000u) ? (u ^ 0x80000000u) : ~u;
    return __uint_as_float(u);
}
__device__ __forceinline__ void ins3(unsigned v, unsigned* p) {
    if (v < p[2]) {
        p[2] = v;
        if (p[2] < p[1]) { unsigned t = p[1]; p[1] = p[2]; p[2] = t; }
        if (p[1] < p[0]) { unsigned t = p[0]; p[0] = p[1]; p[1] = t; }
    }
}

// -------- csq + bf16 codebook + zero stats + ema_cs pre-sum --------
// grid 129 x 256: blocks 0-127 -> 8 codes each (warp per code); block 128 -> ema sum
__global__ void csq_kernel(const float* __restrict__ cb, const float* __restrict__ ema_cs) {
    int b = blockIdx.x;
    int warp = threadIdx.x >> 5;
    int lane = threadIdx.x & 31;
    if (b < 128) {
        int e = b * 8 + warp;
        const float4* src = (const float4*)&cb[(size_t)e * D_DIM];
        float4 v0 = src[lane * 2], v1 = src[lane * 2 + 1];
        ((uint4*)g_cbb32)[e * 32 + lane] =
            make_uint4(bpack(v0.x, v0.y), bpack(v0.z, v0.w),
                       bpack(v1.x, v1.y), bpack(v1.z, v1.w));
        float s = v0.x*v0.x + v0.y*v0.y + v0.z*v0.z + v0.w*v0.w
                + v1.x*v1.x + v1.y*v1.y + v1.z*v1.z + v1.w*v1.w;
        #pragma unroll
        for (int o = 16; o; o >>= 1) s += __shfl_xor_sync(0xffffffffu, s, o);
        float4 z4 = make_float4(0.f, 0.f, 0.f, 0.f);
        ((float4*)&g_embed[(size_t)e * D_DIM])[lane]      = z4;
        ((float4*)&g_embed[(size_t)e * D_DIM])[lane + 32] = z4;
        if (lane == 0) { g_csq[e] = s; g_counts[e] = 0.f; }
    } else {
        __shared__ float ws[8];
        float s = 0.f;
        for (int i = threadIdx.x; i < E_NUM; i += 256) s += ema_cs[i];
        #pragma unroll
        for (int o = 16; o; o >>= 1) s += __shfl_xor_sync(0xffffffffu, s, o);
        if (lane == 0) ws[warp] = s;
        __syncthreads();
        if (threadIdx.x == 0) {
            float t = 0.f;
            #pragma unroll
            for (int i = 0; i < 8; i++) t += ws[i];
            g_nb = t;
            g_loss = 0.f;
        }
    }
}

// -------- bf16 HMMA GEMM + register top-3 + margin-gated exact rescore --------
// 256 threads = 8 warps; block tile 128 rows x 128 codes; warp tile 32x64.
// B streamed in K64 stages (32 stages, double buffered, 16 KB per buffer).
__global__ __launch_bounds__(256, 2) void vq_main_kernel(
    const float* __restrict__ z, const float* __restrict__ cb,
    float* __restrict__ idx_f_out, float* __restrict__ zq_out)
{
    extern __shared__ char smem[];
    const uint32_t sb  = smem_u32(smem);
    const uint32_t sbA = sb + SMEM_A_OFF;
    const uint32_t sbB = sb + SMEM_B_OFF;
    unsigned* candsm = (unsigned*)(smem + SMEM_CAND_OFF);

    const int tid  = threadIdx.x;
    const int warp = tid >> 5;
    const int lane = tid & 31;
    const int tig  = lane & 3;
    const int grp  = lane >> 2;
    const int warp_m = (warp & 3) * 32;
    const int wn     = warp >> 2;        // 0/1: column half
    const int warp_n = wn * 64;
    const int row0 = blockIdx.x * 128;

    // fragment addresses (swizzle key collapses to lane&7)
    const int asw = lane & 7;
    const int akx = lane >> 4;
    const int bkx = (lane >> 3) & 1;
    uint32_t aB[2];
    #pragma unroll
    for (int mf = 0; mf < 2; mf++)
        aB[mf] = sbA + (warp_m + mf * 16 + ((lane >> 3) & 1) * 8 + (lane & 7)) * 512;
    uint32_t bBp[4];
    #pragma unroll
    for (int p = 0; p < 4; p++)
        bBp[p] = (uint32_t)((warp_n + p * 16 + (lane >> 4) * 8 + (lane & 7)) * 128);

    // ---- A staging: z rows -> bf16 swizzled smem ----
    #pragma unroll 4
    for (int i = 0; i < 16; i++) {
        int li = tid + i * 256;          // 4096 granules (16B = 8 bf16)
        int r = li >> 5, kg = li & 31;
        const float4* s = (const float4*)&z[(size_t)(row0 + r) * D_DIM + kg * 8];
        float4 v0 = s[0], v1 = s[1];
        *(uint4*)(smem + SMEM_A_OFF + r * 512 + ((kg ^ (r & 7)) << 4)) =
            make_uint4(bpack(v0.x, v0.y), bpack(v0.z, v0.w),
                       bpack(v1.x, v1.y), bpack(v1.z, v1.w));
    }
    // ---- B stage 0 via cp.async (tile 0, K-quarter 0: 16 KB) ----
    {
        const char* src = (const char*)g_cbb32;
        #pragma unroll
        for (int i = 0; i < 4; i++) {
            int li = tid + i * 256;      // 1024 granules
            int r = li >> 3, kg = li & 7;
            cp16(sbB + r * 128 + ((kg ^ (r & 7)) << 4), src + (size_t)r * 512 + kg * 16);
        }
        CP_COMMIT();
    }
    CP_WAIT0();
    __syncthreads();

    float acc[2][8][4];
    #pragma unroll
    for (int mf = 0; mf < 2; mf++)
        #pragma unroll
        for (int nf = 0; nf < 8; nf++)
            #pragma unroll
            for (int q = 0; q < 4; q++) acc[mf][nf][q] = 0.f;

    // persistent per-thread top-3 (u32 packed) for 4 row-slots
    unsigned P[4][3];
    #pragma unroll
    for (int s = 0; s < 4; s++) { P[s][0] = ~0u; P[s][1] = ~0u; P[s][2] = ~0u; }

    int pb = 0;
    #pragma unroll 1
    for (int st = 0; st < 32; st++) {
        const int t = st >> 2, ks = st & 3;

        // issue next B stage (K64)
        if (st < 31) {
            int stn = st + 1, tn = stn >> 2, ksn = stn & 3;
            const char* src = (const char*)g_cbb32 + (size_t)(tn * 128) * 512 + ksn * 128;
            uint32_t dstb = sbB + (pb ^ 1) * 16384;
            #pragma unroll
            for (int i = 0; i < 4; i++) {
                int li = tid + i * 256;
                int r = li >> 3, kg = li & 7;
                cp16(dstb + r * 128 + ((kg ^ (r & 7)) << 4), src + (size_t)r * 512 + kg * 16);
            }
            CP_COMMIT();
        }

        // compute current stage: 4 k16 slices
        const uint32_t bbuf = sbB + pb * 16384;
        #pragma unroll
        for (int k16 = 0; k16 < 4; k16++) {
            uint32_t kb = (uint32_t)(((k16 * 2 + bkx) ^ asw) << 4);
            unsigned bb[4][4];
            #pragma unroll
            for (int p = 0; p < 4; p++)
                LDSM4(bb[p][0], bb[p][1], bb[p][2], bb[p][3], bbuf + bBp[p] + kb);
            int kga = ks * 8 + k16 * 2 + akx;
            #pragma unroll
            for (int mf = 0; mf < 2; mf++) {
                unsigned a0, a1, a2, a3;
                LDSM4(a0, a1, a2, a3, aB[mf] + ((kga ^ asw) << 4));
                #pragma unroll
                for (int p = 0; p < 4; p++) {
                    mma_bf16(acc[mf][p * 2],     a0, a1, a2, a3, bb[p][0], bb[p][1]);
                    mma_bf16(acc[mf][p * 2 + 1], a0, a1, a2, a3, bb[p][2], bb[p][3]);
                }
            }
        }

        // ---- tile epilogue: distances -> per-thread register top-3 ----
        if (ks == 3) {
            int cbase = t * 128 + warp_n + tig * 2;
            #pragma unroll
            for (int nf = 0; nf < 8; nf++) {
                int ca = cbase + nf * 8;
                float cqa = __ldg(&g_csq[ca]);
                float cqb = __ldg(&g_csq[ca + 1]);
                #pragma unroll
                for (int mf = 0; mf < 2; mf++) {
                    #pragma unroll
                    for (int rh = 0; rh < 2; rh++) {
                        int s = mf * 2 + rh;
                        ins3(packdi(cqa - 2.f * acc[mf][nf][rh * 2],     ca),     P[s]);
                        ins3(packdi(cqb - 2.f * acc[mf][nf][rh * 2 + 1], ca + 1), P[s]);
                    }
                }
            }
            #pragma unroll
            for (int mf = 0; mf < 2; mf++)
                #pragma unroll
                for (int nf = 0; nf < 8; nf++)
                    #pragma unroll
                    for (int q = 0; q < 4; q++) acc[mf][nf][q] = 0.f;
        }

        CP_WAIT0();
        __syncthreads();
        pb ^= 1;
    }

    // ---- merge top-3 across tig lanes -> half top-3 per row ----
    #pragma unroll
    for (int s = 0; s < 4; s++) {
        #pragma unroll
        for (int off = 1; off <= 2; off <<= 1) {
            unsigned ov[3];
            #pragma unroll
            for (int j = 0; j < 3; j++)
                ov[j] = __shfl_xor_sync(0xffffffffu, P[s][j], off);
            #pragma unroll
            for (int j = 0; j < 3; j++) ins3(ov[j], P[s]);
        }
        if (tig == 0) {
            int rl = warp_m + (s >> 1) * 16 + (s & 1) * 8 + grp;
            unsigned* c = candsm + (rl * 2 + wn) * 3;
            c[0] = P[s][0]; c[1] = P[s][1]; c[2] = P[s][2];
        }
    }
    __syncthreads();

    // ---- margin-gated exact fp32 rescore + scatter ----
    float lsum_t = 0.f;
    #pragma unroll 1
    for (int j = 0; j < 16; j++) {
        int lrow = warp * 16 + j;
        int row  = row0 + lrow;
        const float4* zp = (const float4*)&z[(size_t)row * D_DIM];
        float4 x0 = zp[lane], x1 = zp[lane + 32];

        // unpack 6 approx candidates (warp-uniform)
        float df[6]; int ei[6];
        #pragma unroll
        for (int c = 0; c < 6; c++) {
            unsigned k = candsm[lrow * 6 + c];
            ei[c] = (int)(k & 1023u);
            df[c] = unpackd(k);
        }
        float bestdf = fminf(df[0], df[3]);   // heads of the two sorted triples
        float thresh = bestdf + RESCORE_MARGIN;

        float bd = FLT_BIG;
        int   bi = 0x7fffffff;
        #pragma unroll 1
        for (int c = 0; c < 6; c++) {
            if (df[c] > thresh) continue;     // warp-uniform branch
            int e = ei[c];
            const float4* cp = (const float4*)&cb[(size_t)e * D_DIM];
            float4 c0 = cp[lane], c1 = cp[lane + 32];
            float dot = x0.x*c0.x + x0.y*c0.y + x0.z*c0.z + x0.w*c0.w
                      + x1.x*c1.x + x1.y*c1.y + x1.z*c1.z + x1.w*c1.w;
            #pragma unroll
            for (int o = 16; o; o >>= 1) dot += __shfl_xor_sync(0xffffffffu, dot, o);
            float d = g_csq[e] - 2.f * dot;
            if (d < bd || (d == bd && e < bi)) { bd = d; bi = e; }
        }
        if (lane == 0) idx_f_out[row] = (float)bi;

        const float4* cp = (const float4*)&cb[(size_t)bi * D_DIM];
        float4 c0 = cp[lane], c1 = cp[lane + 32];
        float4 o0, o1;
        o0.x = x0.x + (c0.x - x0.x); o0.y = x0.y + (c0.y - x0.y);
        o0.z = x0.z + (c0.z - x0.z); o0.w = x0.w + (c0.w - x0.w);
        o1.x = x1.x + (c1.x - x1.x); o1.y = x1.y + (c1.y - x1.y);
        o1.z = x1.z + (c1.z - x1.z); o1.w = x1.w + (c1.w - x1.w);
        float4* qp = (float4*)&zq_out[(size_t)row * D_DIM];
        qp[lane] = o0; qp[lane + 32] = o1;

        float dx;
        dx = x0.x - c0.x; lsum_t += dx * dx;  dx = x0.y - c0.y; lsum_t += dx * dx;
        dx = x0.z - c0.z; lsum_t += dx * dx;  dx = x0.w - c0.w; lsum_t += dx * dx;
        dx = x1.x - c1.x; lsum_t += dx * dx;  dx = x1.y - c1.y; lsum_t += dx * dx;
        dx = x1.z - c1.z; lsum_t += dx * dx;  dx = x1.w - c1.w; lsum_t += dx * dx;

        float* ge = &g_embed[(size_t)bi * D_DIM];
        asm volatile("red.global.add.v4.f32 [%0], {%1,%2,%3,%4};"
                     :: "l"(ge + lane * 4), "f"(x0.x), "f"(x0.y), "f"(x0.z), "f"(x0.w) : "memory");
        asm volatile("red.global.add.v4.f32 [%0], {%1,%2,%3,%4};"
                     :: "l"(ge + (lane + 32) * 4), "f"(x1.x), "f"(x1.y), "f"(x1.z), "f"(x1.w) : "memory");
        if (lane == 0) atomicAdd(&g_counts[bi], 1.0f);
    }
    #pragma unroll
    for (int o = 16; o; o >>= 1) lsum_t += __shfl_xor_sync(0xffffffffu, lsum_t, o);
    if (lane == 0) atomicAdd(&g_loss, lsum_t);
}

// -------- merged finalize (vector loads, scalar stores: outputs odd-offset) --------
__global__ void finalize_kernel(const float* __restrict__ ema_cs,
                                const float* __restrict__ ema_es,
                                float* __restrict__ out_cb,
                                float* __restrict__ out_cs,
                                float* __restrict__ out_es,
                                float* __restrict__ out_loss)
{
    int e = blockIdx.x * 4 + (threadIdx.x >> 6);
    int q = threadIdx.x & 63;
    float n = DECAY_F * g_nb + OMD_F * (float)N_TOT;
    float ncs = DECAY_F * ema_cs[e] + OMD_F * g_counts[e];
    float inv_sm = (n + 1024.0f * 1e-5f) / ((ncs + 1e-5f) * n);
    size_t base = (size_t)e * D_DIM + q * 4;
    float4 es = *(const float4*)&ema_es[base];
    float4 ge = *(const float4*)&g_embed[base];
    float nes0 = DECAY_F * es.x + OMD_F * ge.x;
    float nes1 = DECAY_F * es.y + OMD_F * ge.y;
    float nes2 = DECAY_F * es.z + OMD_F * ge.z;
    float nes3 = DECAY_F * es.w + OMD_F * ge.w;
    out_es[base + 0] = nes0;  out_cb[base + 0] = nes0 * inv_sm;
    out_es[base + 1] = nes1;  out_cb[base + 1] = nes1 * inv_sm;
    out_es[base + 2] = nes2;  out_cb[base + 2] = nes2 * inv_sm;
    out_es[base + 3] = nes3;  out_cb[base + 3] = nes3 * inv_sm;
    if (q == 0) {
        out_cs[e] = ncs;
        if (e == 0) *out_loss = 0.5f * g_loss / (float)(N_TOT * D_DIM);
    }
}

extern "C" void kernel_launch(void* const* d_in, const int* in_sizes, int n_in,
                              void* d_out, int out_size)
{
    const float* z_e    = (const float*)d_in[0];
    const float* cb     = (const float*)d_in[1];
    const float* ema_cs = (const float*)d_in[2];
    const float* ema_es = (const float*)d_in[3];
    float* out = (float*)d_out;

    float* out_zq   = out;
    float* out_loss = out + ZQ_ELEMS;
    float* out_idx  = out + ZQ_ELEMS + 1;
    float* out_cb   = out + ZQ_ELEMS + 1 + N_TOT;
    float* out_cs   = out_cb + E_NUM * D_DIM;
    float* out_es   = out_cs + E_NUM;

    cudaFuncSetAttribute(vq_main_kernel,
                         cudaFuncAttributeMaxDynamicSharedMemorySize, SMEM_TOTAL);

    csq_kernel<<<129, 256>>>(cb, ema_cs);
    vq_main_kernel<<<N_TOT / 128, 256, SMEM_TOTAL>>>(z_e, cb, out_idx, out_zq);
    finalize_kernel<<<E_NUM / 4, 256>>>(ema_cs, ema_es, out_cb, out_cs, out_es, out_loss);
}

// round 16
// speedup vs baseline: 2.0355x; 1.0409x over previous
#include <cuda_runtime.h>
#include <cstdint>

#define E_NUM 1024
#define D_DIM 256
#define N_TOT 32768
#define ZQ_ELEMS 8388608
#define DECAY_F 0.99f
#define OMD_F 0.01f
#define FLT_BIG 3.4e38f

// ---- dynamic smem layout (main kernel) ----
#define SMEM_A_OFF    0        // 65536 : A 128x256 bf16, swizzled
#define SMEM_B_OFF    65536    // 32768 : B double buffer, 2 x (128 codes x 64 k bf16)
#define SMEM_CAND_OFF 98304    // 3072  : cand [128 rows][2 halves][3] u32
#define SMEM_TOTAL    101376

// -------- device scratch (no allocations allowed) --------
// zero-initialized at module load; finalize re-zeroes after reading each launch
__device__ float g_counts[E_NUM];
__device__ __align__(16) float g_embed[E_NUM * D_DIM];
__device__ float g_csq[E_NUM];
__device__ float g_loss;
__device__ float g_nb;
__device__ __align__(16) unsigned g_cbb32[E_NUM * D_DIM / 2];   // codebook bf16

// -------- helpers --------
__device__ __forceinline__ uint32_t smem_u32(const void* p) {
    uint32_t a;
    asm("{ .reg .u64 t; cvta.to.shared.u64 t, %1; cvt.u32.u64 %0, t; }" : "=r"(a) : "l"(p));
    return a;
}
__device__ __forceinline__ unsigned bpack(float lo, float hi) {
    unsigned r;
    asm("cvt.rn.bf16x2.f32 %0, %1, %2;" : "=r"(r) : "f"(hi), "f"(lo));
    return r;
}
__device__ __forceinline__ void mma_bf16(float* c, unsigned a0, unsigned a1, unsigned a2,
                                         unsigned a3, unsigned b0, unsigned b1) {
    asm volatile("mma.sync.aligned.m16n8k16.row.col.f32.bf16.bf16.f32 "
        "{%0,%1,%2,%3}, {%4,%5,%6,%7}, {%8,%9}, {%0,%1,%2,%3};"
        : "+f"(c[0]), "+f"(c[1]), "+f"(c[2]), "+f"(c[3])
        : "r"(a0), "r"(a1), "r"(a2), "r"(a3), "r"(b0), "r"(b1));
}
#define LDSM4(r0,r1,r2,r3,addr) \
    asm volatile("ldmatrix.sync.aligned.m8n8.x4.shared.b16 {%0,%1,%2,%3}, [%4];" \
        : "=r"(r0), "=r"(r1), "=r"(r2), "=r"(r3) : "r"(addr))
__device__ __forceinline__ void cp16(unsigned dst, const void* src) {
    asm volatile("cp.async.ca.shared.global [%0], [%1], 16;"
                 :: "r"(dst), "l"(__cvta_generic_to_global(src)) : "memory");
}
#define CP_COMMIT() asm volatile("cp.async.commit_group;" ::: "memory")
#define CP_WAIT0()  asm volatile("cp.async.wait_group 0;" ::: "memory")

// u32 key: orderable-f32(dist) top 22 bits | idx (10 bits). ascending == (dist, idx)
__device__ __forceinline__ unsigned packdi(float d, int idx) {
    unsigned u = __float_as_uint(d);
    u ^= (unsigned)(((int)u) >> 31) | 0x80000000u;
    return (u & 0xFFFFFC00u) | (unsigned)idx;
}
__device__ __forceinline__ void ins3(unsigned v, unsigned* p) {
    if (v < p[2]) {
        p[2] = v;
        if (p[2] < p[1]) { unsigned t = p[1]; p[1] = p[2]; p[2] = t; }
        if (p[1] < p[0]) { unsigned t = p[0]; p[0] = p[1]; p[1] = t; }
    }
}

// -------- csq + bf16 codebook + ema_cs pre-sum (NO zeroing: finalize owns it) --------
// grid 129 x 256: blocks 0-127 -> 8 codes each (warp per code); block 128 -> ema sum
__global__ void csq_kernel(const float* __restrict__ cb, const float* __restrict__ ema_cs) {
    int b = blockIdx.x;
    int warp = threadIdx.x >> 5;
    int lane = threadIdx.x & 31;
    if (b < 128) {
        int e = b * 8 + warp;
        const float4* src = (const float4*)&cb[(size_t)e * D_DIM];
        float4 v0 = src[lane * 2], v1 = src[lane * 2 + 1];
        ((uint4*)g_cbb32)[e * 32 + lane] =
            make_uint4(bpack(v0.x, v0.y), bpack(v0.z, v0.w),
                       bpack(v1.x, v1.y), bpack(v1.z, v1.w));
        float s = v0.x*v0.x + v0.y*v0.y + v0.z*v0.z + v0.w*v0.w
                + v1.x*v1.x + v1.y*v1.y + v1.z*v1.z + v1.w*v1.w;
        #pragma unroll
        for (int o = 16; o; o >>= 1) s += __shfl_xor_sync(0xffffffffu, s, o);
        if (lane == 0) g_csq[e] = s;
    } else {
        __shared__ float ws[8];
        float s = 0.f;
        for (int i = threadIdx.x; i < E_NUM; i += 256) s += ema_cs[i];
        #pragma unroll
        for (int o = 16; o; o >>= 1) s += __shfl_xor_sync(0xffffffffu, s, o);
        if (lane == 0) ws[warp] = s;
        __syncthreads();
        if (threadIdx.x == 0) {
            float t = 0.f;
            #pragma unroll
            for (int i = 0; i < 8; i++) t += ws[i];
            g_nb = t;
        }
    }
}

// -------- bf16 HMMA GEMM + register top-3 + fused exact rescore/scatter --------
// 256 threads = 8 warps; block tile 128 rows x 128 codes; warp tile 32x64.
// B streamed in K64 stages (32 stages, double buffered, 16 KB per buffer).
__global__ __launch_bounds__(256, 2) void vq_main_kernel(
    const float* __restrict__ z, const float* __restrict__ cb,
    float* __restrict__ idx_f_out, float* __restrict__ zq_out)
{
    extern __shared__ char smem[];
    const uint32_t sb  = smem_u32(smem);
    const uint32_t sbA = sb + SMEM_A_OFF;
    const uint32_t sbB = sb + SMEM_B_OFF;
    unsigned* candsm = (unsigned*)(smem + SMEM_CAND_OFF);

    const int tid  = threadIdx.x;
    const int warp = tid >> 5;
    const int lane = tid & 31;
    const int tig  = lane & 3;
    const int grp  = lane >> 2;
    const int warp_m = (warp & 3) * 32;
    const int wn     = warp >> 2;        // 0/1: column half
    const int warp_n = wn * 64;
    const int row0 = blockIdx.x * 128;

    // fragment addresses (swizzle key collapses to lane&7)
    const int asw = lane & 7;
    const int akx = lane >> 4;
    const int bkx = (lane >> 3) & 1;
    uint32_t aB[2];
    #pragma unroll
    for (int mf = 0; mf < 2; mf++)
        aB[mf] = sbA + (warp_m + mf * 16 + ((lane >> 3) & 1) * 8 + (lane & 7)) * 512;
    uint32_t bBp[4];
    #pragma unroll
    for (int p = 0; p < 4; p++)
        bBp[p] = (uint32_t)((warp_n + p * 16 + (lane >> 4) * 8 + (lane & 7)) * 128);

    // ---- A staging: z rows -> bf16 swizzled smem ----
    #pragma unroll 4
    for (int i = 0; i < 16; i++) {
        int li = tid + i * 256;          // 4096 granules (16B = 8 bf16)
        int r = li >> 5, kg = li & 31;
        const float4* s = (const float4*)&z[(size_t)(row0 + r) * D_DIM + kg * 8];
        float4 v0 = s[0], v1 = s[1];
        *(uint4*)(smem + SMEM_A_OFF + r * 512 + ((kg ^ (r & 7)) << 4)) =
            make_uint4(bpack(v0.x, v0.y), bpack(v0.z, v0.w),
                       bpack(v1.x, v1.y), bpack(v1.z, v1.w));
    }
    // ---- B stage 0 via cp.async (tile 0, K-quarter 0: 16 KB) ----
    {
        const char* src = (const char*)g_cbb32;
        #pragma unroll
        for (int i = 0; i < 4; i++) {
            int li = tid + i * 256;      // 1024 granules
            int r = li >> 3, kg = li & 7;
            cp16(sbB + r * 128 + ((kg ^ (r & 7)) << 4), src + (size_t)r * 512 + kg * 16);
        }
        CP_COMMIT();
    }
    CP_WAIT0();
    __syncthreads();

    float acc[2][8][4];
    #pragma unroll
    for (int mf = 0; mf < 2; mf++)
        #pragma unroll
        for (int nf = 0; nf < 8; nf++)
            #pragma unroll
            for (int q = 0; q < 4; q++) acc[mf][nf][q] = 0.f;

    // persistent per-thread top-3 (u32 packed) for 4 row-slots
    unsigned P[4][3];
    #pragma unroll
    for (int s = 0; s < 4; s++) { P[s][0] = ~0u; P[s][1] = ~0u; P[s][2] = ~0u; }

    int pb = 0;
    #pragma unroll 1
    for (int st = 0; st < 32; st++) {
        const int t = st >> 2, ks = st & 3;

        // issue next B stage (K64)
        if (st < 31) {
            int stn = st + 1, tn = stn >> 2, ksn = stn & 3;
            const char* src = (const char*)g_cbb32 + (size_t)(tn * 128) * 512 + ksn * 128;
            uint32_t dstb = sbB + (pb ^ 1) * 16384;
            #pragma unroll
            for (int i = 0; i < 4; i++) {
                int li = tid + i * 256;
                int r = li >> 3, kg = li & 7;
                cp16(dstb + r * 128 + ((kg ^ (r & 7)) << 4), src + (size_t)r * 512 + kg * 16);
            }
            CP_COMMIT();
        }

        // compute current stage: 4 k16 slices
        const uint32_t bbuf = sbB + pb * 16384;
        #pragma unroll
        for (int k16 = 0; k16 < 4; k16++) {
            uint32_t kb = (uint32_t)(((k16 * 2 + bkx) ^ asw) << 4);
            unsigned bb[4][4];
            #pragma unroll
            for (int p = 0; p < 4; p++)
                LDSM4(bb[p][0], bb[p][1], bb[p][2], bb[p][3], bbuf + bBp[p] + kb);
            int kga = ks * 8 + k16 * 2 + akx;
            #pragma unroll
            for (int mf = 0; mf < 2; mf++) {
                unsigned a0, a1, a2, a3;
                LDSM4(a0, a1, a2, a3, aB[mf] + ((kga ^ asw) << 4));
                #pragma unroll
                for (int p = 0; p < 4; p++) {
                    mma_bf16(acc[mf][p * 2],     a0, a1, a2, a3, bb[p][0], bb[p][1]);
                    mma_bf16(acc[mf][p * 2 + 1], a0, a1, a2, a3, bb[p][2], bb[p][3]);
                }
            }
        }

        // ---- tile epilogue: distances -> per-thread register top-3 ----
        if (ks == 3) {
            int cbase = t * 128 + warp_n + tig * 2;
            #pragma unroll
            for (int nf = 0; nf < 8; nf++) {
                int ca = cbase + nf * 8;
                float cqa = __ldg(&g_csq[ca]);
                float cqb = __ldg(&g_csq[ca + 1]);
                #pragma unroll
                for (int mf = 0; mf < 2; mf++) {
                    #pragma unroll
                    for (int rh = 0; rh < 2; rh++) {
                        int s = mf * 2 + rh;
                        ins3(packdi(cqa - 2.f * acc[mf][nf][rh * 2],     ca),     P[s]);
                        ins3(packdi(cqb - 2.f * acc[mf][nf][rh * 2 + 1], ca + 1), P[s]);
                    }
                }
            }
            #pragma unroll
            for (int mf = 0; mf < 2; mf++)
                #pragma unroll
                for (int nf = 0; nf < 8; nf++)
                    #pragma unroll
                    for (int q = 0; q < 4; q++) acc[mf][nf][q] = 0.f;
        }

        CP_WAIT0();
        __syncthreads();
        pb ^= 1;
    }

    // ---- merge top-3 across tig lanes -> half top-3 per row ----
    #pragma unroll
    for (int s = 0; s < 4; s++) {
        #pragma unroll
        for (int off = 1; off <= 2; off <<= 1) {
            unsigned ov[3];
            #pragma unroll
            for (int j = 0; j < 3; j++)
                ov[j] = __shfl_xor_sync(0xffffffffu, P[s][j], off);
            #pragma unroll
            for (int j = 0; j < 3; j++) ins3(ov[j], P[s]);
        }
        if (tig == 0) {
            int rl = warp_m + (s >> 1) * 16 + (s & 1) * 8 + grp;
            unsigned* c = candsm + (rl * 2 + wn) * 3;
            c[0] = P[s][0]; c[1] = P[s][1]; c[2] = P[s][2];
        }
    }
    __syncthreads();

    // ---- fused exact fp32 rescore of 6 candidates + scatter ----
    float lsum_t = 0.f;
    #pragma unroll 1
    for (int j = 0; j < 16; j++) {
        int lrow = warp * 16 + j;
        int row  = row0 + lrow;
        const float4* zp = (const float4*)&z[(size_t)row * D_DIM];
        float4 x0 = zp[lane], x1 = zp[lane + 32];

        float bd = FLT_BIG;
        int   bi = 0x7fffffff;
        #pragma unroll
        for (int c = 0; c < 6; c++) {
            int e = (int)(candsm[lrow * 6 + c] & 1023u);
            const float4* cp = (const float4*)&cb[(size_t)e * D_DIM];
            float4 c0 = cp[lane], c1 = cp[lane + 32];
            float dot = x0.x*c0.x + x0.y*c0.y + x0.z*c0.z + x0.w*c0.w
                      + x1.x*c1.x + x1.y*c1.y + x1.z*c1.z + x1.w*c1.w;
            #pragma unroll
            for (int o = 16; o; o >>= 1) dot += __shfl_xor_sync(0xffffffffu, dot, o);
            float d = g_csq[e] - 2.f * dot;
            if (d < bd || (d == bd && e < bi)) { bd = d; bi = e; }
        }
        if (lane == 0) idx_f_out[row] = (float)bi;

        const float4* cp = (const float4*)&cb[(size_t)bi * D_DIM];
        float4 c0 = cp[lane], c1 = cp[lane + 32];
        float4 o0, o1;
        o0.x = x0.x + (c0.x - x0.x); o0.y = x0.y + (c0.y - x0.y);
        o0.z = x0.z + (c0.z - x0.z); o0.w = x0.w + (c0.w - x0.w);
        o1.x = x1.x + (c1.x - x1.x); o1.y = x1.y + (c1.y - x1.y);
        o1.z = x1.z + (c1.z - x1.z); o1.w = x1.w + (c1.w - x1.w);
        float4* qp = (float4*)&zq_out[(size_t)row * D_DIM];
        qp[lane] = o0; qp[lane + 32] = o1;

        float dx;
        dx = x0.x - c0.x; lsum_t += dx * dx;  dx = x0.y - c0.y; lsum_t += dx * dx;
        dx = x0.z - c0.z; lsum_t += dx * dx;  dx = x0.w - c0.w; lsum_t += dx * dx;
        dx = x1.x - c1.x; lsum_t += dx * dx;  dx = x1.y - c1.y; lsum_t += dx * dx;
        dx = x1.z - c1.z; lsum_t += dx * dx;  dx = x1.w - c1.w; lsum_t += dx * dx;

        float* ge = &g_embed[(size_t)bi * D_DIM];
        asm volatile("red.global.add.v4.f32 [%0], {%1,%2,%3,%4};"
                     :: "l"(ge + lane * 4), "f"(x0.x), "f"(x0.y), "f"(x0.z), "f"(x0.w) : "memory");
        asm volatile("red.global.add.v4.f32 [%0], {%1,%2,%3,%4};"
                     :: "l"(ge + (lane + 32) * 4), "f"(x1.x), "f"(x1.y), "f"(x1.z), "f"(x1.w) : "memory");
        if (lane == 0) atomicAdd(&g_counts[bi], 1.0f);
    }
    #pragma unroll
    for (int o = 16; o; o >>= 1) lsum_t += __shfl_xor_sync(0xffffffffu, lsum_t, o);
    if (lane == 0) atomicAdd(&g_loss, lsum_t);
}

// -------- merged finalize: EMA outputs + read-then-zero the accumulators --------
__global__ void finalize_kernel(const float* __restrict__ ema_cs,
                                const float* __restrict__ ema_es,
                                float* __restrict__ out_cb,
                                float* __restrict__ out_cs,
                                float* __restrict__ out_es,
                                float* __restrict__ out_loss)
{
    int e = blockIdx.x * 4 + (threadIdx.x >> 6);
    int q = threadIdx.x & 63;
    float n = DECAY_F * g_nb + OMD_F * (float)N_TOT;
    float ncs = DECAY_F * ema_cs[e] + OMD_F * g_counts[e];
    float inv_sm = (n + 1024.0f * 1e-5f) / ((ncs + 1e-5f) * n);
    size_t base = (size_t)e * D_DIM + q * 4;
    float4 es = *(const float4*)&ema_es[base];
    float4 ge = *(const float4*)&g_embed[base];
    // re-zero accumulators for the next graph replay
    *(float4*)&g_embed[base] = make_float4(0.f, 0.f, 0.f, 0.f);
    float nes0 = DECAY_F * es.x + OMD_F * ge.x;
    float nes1 = DECAY_F * es.y + OMD_F * ge.y;
    float nes2 = DECAY_F * es.z + OMD_F * ge.z;
    float nes3 = DECAY_F * es.w + OMD_F * ge.w;
    out_es[base + 0] = nes0;  out_cb[base + 0] = nes0 * inv_sm;
    out_es[base + 1] = nes1;  out_cb[base + 1] = nes1 * inv_sm;
    out_es[base + 2] = nes2;  out_cb[base + 2] = nes2 * inv_sm;
    out_es[base + 3] = nes3;  out_cb[base + 3] = nes3 * inv_sm;
    if (q == 0) {
        out_cs[e] = ncs;
        g_counts[e] = 0.f;
        if (e == 0) {
            *out_loss = 0.5f * g_loss / (float)(N_TOT * D_DIM);
            g_loss = 0.f;
        }
    }
}

extern "C" void kernel_launch(void* const* d_in, const int* in_sizes, int n_in,
                              void* d_out, int out_size)
{
    const float* z_e    = (const float*)d_in[0];
    const float* cb     = (const float*)d_in[1];
    const float* ema_cs = (const float*)d_in[2];
    const float* ema_es = (const float*)d_in[3];
    float* out = (float*)d_out;

    float* out_zq   = out;
    float* out_loss = out + ZQ_ELEMS;
    float* out_idx  = out + ZQ_ELEMS + 1;
    float* out_cb   = out + ZQ_ELEMS + 1 + N_TOT;
    float* out_cs   = out_cb + E_NUM * D_DIM;
    float* out_es   = out_cs + E_NUM;

    cudaFuncSetAttribute(vq_main_kernel,
                         cudaFuncAttributeMaxDynamicSharedMemorySize, SMEM_TOTAL);

    csq_kernel<<<129, 256>>>(cb, ema_cs);
    vq_main_kernel<<<N_TOT / 128, 256, SMEM_TOTAL>>>(z_e, cb, out_idx, out_zq);
    finalize_kernel<<<E_NUM / 4, 256>>>(ema_cs, ema_es, out_cb, out_cs, out_es, out_loss);
}